// round 11
// baseline (speedup 1.0000x reference)
#include <cuda_runtime.h>
#include <cuda_bf16.h>
#include <math.h>
#include <stdint.h>

#define SZ 160
#define NB 8
#define NC 64
#define HW 256
#define NCH 16          // split-K channel chunks
#define CPB (NC / NCH)  // 4 channels per block

// -------- scratch (no allocations allowed; __device__ globals) --------
__device__ float g_x160[NB * NC * SZ * SZ];            // 52.4 MB
__device__ float g_part[2 * NCH * NB * NC * SZ];       // fp32 split-K partials
__device__ float g_bvec[NB * NC * SZ];
__device__ float g_cvec[NB * NC * SZ];
__device__ float g_s[NB * NC];

// ---------------- Kernel 1: nearest downsample 256->160 ----------------
__global__ void k_down(const float* __restrict__ x) {
    int bc = blockIdx.x;
    const float* __restrict__ src = x + (size_t)bc * HW * HW;
    float* __restrict__ dst = g_x160 + (size_t)bc * SZ * SZ;
    for (int e = threadIdx.x; e < SZ * SZ; e += blockDim.x) {
        int h = e / SZ;
        int w = e - h * SZ;
        dst[e] = __ldg(&src[((h * 8) / 5) * HW + (w * 8) / 5]);
    }
}

// ---------------- Kernel 2: warp-level HMMA bf16-split GEMM ----------------
// D[m,o] = sum_{c,k} x[m,(c,k)] * W[o,(c,k)];  x=hi+lo, W=hi+lo (bf16);
// hi*hi + hi*lo + lo*hi in fp32 accum (lo*lo dropped).
// Staging: coalesced global loads -> convert once -> padded smem [row][kp(17)]
// (u32 = bf16 pair for k=2kp,2kp+1). Compute: per-lane LDS.32 fragment gathers.
// m16n8k16.row.col mapping (lane L, q=L&3, r=L>>2):
//   A reg j: row = r+(j&1)*8,  kp = q+(j>>1)*4 (+ks*8)
//   B reg j: kp  = q+j*4 (+ks*8), col = r
//   C reg j: row = r+(j>>1)*8, col = 2q+(j&1)

__device__ __forceinline__ uint32_t pack_hi(float a, float b) {
    __nv_bfloat162 h = __floats2bfloat162_rn(a, b);
    return *(uint32_t*)&h;
}
__device__ __forceinline__ uint32_t pack_lo(float a, float b) {
    __nv_bfloat16 ha = __float2bfloat16(a), hb = __float2bfloat16(b);
    __nv_bfloat16 la = __float2bfloat16(a - __bfloat162float(ha));
    __nv_bfloat16 lb = __float2bfloat16(b - __bfloat162float(hb));
    return ((uint32_t)__bfloat16_as_ushort(lb) << 16) | __bfloat16_as_ushort(la);
}
__device__ __forceinline__ void hmma(float* c, const uint32_t* a, const uint32_t* b) {
    asm volatile(
        "mma.sync.aligned.m16n8k16.row.col.f32.bf16.bf16.f32 "
        "{%0,%1,%2,%3}, {%4,%5,%6,%7}, {%8,%9}, {%0,%1,%2,%3};"
        : "+f"(c[0]), "+f"(c[1]), "+f"(c[2]), "+f"(c[3])
        : "r"(a[0]), "r"(a[1]), "r"(a[2]), "r"(a[3]), "r"(b[0]), "r"(b[1]));
}

#define KP 17   // padded pair-pitch

__global__ __launch_bounds__(256, 2)
void k_mma(const float* __restrict__ WbP, const float* __restrict__ WcP) {
    __shared__ uint32_t Ahi[SZ * KP];   // 10880 B
    __shared__ uint32_t Alo[SZ * KP];
    __shared__ uint32_t Bhi[64 * KP];   //  4352 B
    __shared__ uint32_t Blo[64 * KP];   // total ~30.5 KB

    const int cc    = blockIdx.x;   // 0..NCH-1
    const int batch = blockIdx.y;   // 0..7
    const int which = blockIdx.z;   // 0 or 1
    const float* __restrict__ W = which ? WcP : WbP;

    const int t    = threadIdx.x;
    const int wid  = t >> 5;
    const int lane = t & 31;
    const int mgrp = wid >> 2;      // 0..1 -> m rows [80*mgrp, +80)
    const int ngrp = wid & 3;       // 0..3 -> n tiles ngrp*2, +1
    const int q = lane & 3, r = lane >> 2;

    float acc[5][2][4];
#pragma unroll
    for (int i = 0; i < 5; i++)
#pragma unroll
        for (int j = 0; j < 2; j++)
#pragma unroll
            for (int rr = 0; rr < 4; rr++) acc[i][j][rr] = 0.f;

    for (int slice = 0; slice < CPB * 5; slice++) {
        const int c  = cc * CPB + slice / 5;
        const int k0 = (slice % 5) * 32;
        const float* __restrict__ xb = g_x160 + (size_t)(batch * NC + c) * SZ * SZ;
        const float* __restrict__ wb = W + (size_t)c * SZ;

        // ---- stage A (coalesced) ----
        if (which == 0) {
            // A[m][k] = x[m][k]: rows contiguous in k -> float2
            for (int e = t; e < SZ * 16; e += 256) {
                int kp = e & 15, m = e >> 4;
                float2 v = *(const float2*)&xb[m * SZ + k0 + 2 * kp];
                Ahi[m * KP + kp] = pack_hi(v.x, v.y);
                Alo[m * KP + kp] = pack_lo(v.x, v.y);
            }
        } else {
            // A[m][k] = x[k][m]: rows of x contiguous in m -> 4B coalesced,
            // b16 half-stores into the packed pair word (k&1 selects half).
            for (int e = t; e < 32 * SZ; e += 256) {
                int m = e % SZ, k = e / SZ;
                float v = xb[(k0 + k) * SZ + m];
                __nv_bfloat16 h = __float2bfloat16(v);
                __nv_bfloat16 l = __float2bfloat16(v - __bfloat162float(h));
                int wd = m * KP + (k >> 1);
                ((__nv_bfloat16*)Ahi)[2 * wd + (k & 1)] = h;
                ((__nv_bfloat16*)Alo)[2 * wd + (k & 1)] = l;
            }
        }
        // ---- stage B (coalesced) ----
        for (int e = t; e < 64 * 16; e += 256) {
            int kp = e & 15, o = e >> 4;
            float2 v = *(const float2*)&wb[(size_t)o * (NC * SZ) + k0 + 2 * kp];
            Bhi[o * KP + kp] = pack_hi(v.x, v.y);
            Blo[o * KP + kp] = pack_lo(v.x, v.y);
        }
        __syncthreads();

        // ---- compute: 2 ks x 5 m x 2 n x 3 terms = 60 HMMA ----
#pragma unroll
        for (int ks = 0; ks < 2; ks++) {
            const int kb = q + ks * 8;
            uint32_t bh[2][2], bl[2][2];
#pragma unroll
            for (int ntl = 0; ntl < 2; ntl++) {
                int ob = (ngrp * 2 + ntl) * 8 + r;
                bh[ntl][0] = Bhi[ob * KP + kb];
                bh[ntl][1] = Bhi[ob * KP + kb + 4];
                bl[ntl][0] = Blo[ob * KP + kb];
                bl[ntl][1] = Blo[ob * KP + kb + 4];
            }
#pragma unroll
            for (int mtl = 0; mtl < 5; mtl++) {
                int m0r = (mgrp * 5 + mtl) * 16 + r;
                uint32_t ah[4], al[4];
                ah[0] = Ahi[m0r * KP + kb];
                ah[1] = Ahi[(m0r + 8) * KP + kb];
                ah[2] = Ahi[m0r * KP + kb + 4];
                ah[3] = Ahi[(m0r + 8) * KP + kb + 4];
                al[0] = Alo[m0r * KP + kb];
                al[1] = Alo[(m0r + 8) * KP + kb];
                al[2] = Alo[m0r * KP + kb + 4];
                al[3] = Alo[(m0r + 8) * KP + kb + 4];
#pragma unroll
                for (int ntl = 0; ntl < 2; ntl++) {
                    hmma(acc[mtl][ntl], ah, bh[ntl]);
                    hmma(acc[mtl][ntl], ah, bl[ntl]);
                    hmma(acc[mtl][ntl], al, bh[ntl]);
                }
            }
        }
        __syncthreads();
    }

    // ---- write partials: pout[o*SZ + m] ----
    float* __restrict__ pout =
        g_part + ((size_t)(which * NCH + cc) * NB + batch) * (NC * SZ);
#pragma unroll
    for (int mtl = 0; mtl < 5; mtl++) {
#pragma unroll
        for (int ntl = 0; ntl < 2; ntl++) {
#pragma unroll
            for (int reg = 0; reg < 4; reg++) {
                int m = mgrp * 80 + mtl * 16 + r + (reg >> 1) * 8;
                int o = (ngrp * 2 + ntl) * 8 + q * 2 + (reg & 1);
                pout[o * SZ + m] = acc[mtl][ntl][reg];
            }
        }
    }
}

// ---------------- Kernel 3: reduce partials, BN-fold, SiLU, s = <b,c> ----------------
__global__ void k_finish(const float* __restrict__ gb, const float* __restrict__ bb,
                         const float* __restrict__ gc, const float* __restrict__ bc) {
    const int o     = blockIdx.x;
    const int batch = blockIdx.y;
    const int t     = threadIdx.x;  // 0..159

    float bsum = 0.f, csum = 0.f;
    const size_t inner = (size_t)o * SZ + t;
    for (int cc = 0; cc < NCH; cc++) {
        bsum += g_part[((size_t)(cc) * NB + batch) * (NC * SZ) + inner];
        csum += g_part[((size_t)(NCH + cc) * NB + batch) * (NC * SZ) + inner];
    }
    float bp = bsum * gb[o] + bb[o];
    float bv = bp / (1.f + expf(-bp));
    float cp = csum * gc[o] + bc[o];
    float cv = cp / (1.f + expf(-cp));

    const size_t idx = (size_t)(batch * NC + o) * SZ + t;
    g_bvec[idx] = bv;
    g_cvec[idx] = cv;

    __shared__ float red[SZ];
    red[t] = bv * cv;
    __syncthreads();
    if (t == 0) {
        float s = 0.f;
        for (int i = 0; i < SZ; i++) s += red[i];
        g_s[batch * NC + o] = s;
    }
}

// ---------------- Kernel 4: rank-1 update + upsample, 4-way Y-split ----------------
__global__ __launch_bounds__(256, 6)
void k_final(float* __restrict__ out) {
    __shared__ float bv[SZ];
    __shared__ float cvE[HW];
    __shared__ float ps[40];

    const int bc = blockIdx.x;
    const int q  = blockIdx.y;
    const int t  = threadIdx.x;
    const float* __restrict__ xsrc = g_x160 + (size_t)bc * SZ * SZ;

    if (t < SZ) bv[t] = g_bvec[(size_t)bc * SZ + t];
    cvE[t] = g_cvec[(size_t)bc * SZ + ((t * 5) >> 3)];
    __syncthreads();

    const float sval = g_s[bc];
    const int warp = t >> 5, lane = t & 31;
    for (int hh = warp; hh < 40; hh += 8) {
        const int h = 40 * q + hh;
        float p = 0.f;
#pragma unroll
        for (int k = 0; k < 5; k++) {
            int w = lane + 32 * k;
            p += xsrc[h * SZ + w] * bv[w];
        }
#pragma unroll
        for (int off = 16; off; off >>= 1) p += __shfl_down_sync(0xffffffffu, p, off);
        if (lane == 0) ps[hh] = p * sval;
    }
    __syncthreads();

    const int r  = t >> 6;
    const int xq = t & 63;
    const int X0 = xq * 4;
    const int wi0 = (X0 * 5) >> 3;
    const int wi1 = ((X0 + 1) * 5) >> 3;
    const int wi2 = ((X0 + 2) * 5) >> 3;
    const int wi3 = ((X0 + 3) * 5) >> 3;
    const float c0 = cvE[X0], c1 = cvE[X0 + 1], c2 = cvE[X0 + 2], c3 = cvE[X0 + 3];

    float* __restrict__ obase = out + (size_t)bc * HW * HW;
    const int Ybeg = 64 * q;
#pragma unroll 2
    for (int Y0 = Ybeg; Y0 < Ybeg + 64; Y0 += 4) {
        const int Y = Y0 + r;
        const int h = (Y * 5) >> 3;
        const float* __restrict__ xr = xsrc + h * SZ;
        const float pv = ps[h - 40 * q];
        float4 v;
        v.x = xr[wi0] + pv * c0;
        v.y = xr[wi1] + pv * c1;
        v.z = xr[wi2] + pv * c2;
        v.w = xr[wi3] + pv * c3;
        *(float4*)&obase[Y * HW + X0] = v;
    }
}

// ---------------- launch ----------------
extern "C" void kernel_launch(void* const* d_in, const int* in_sizes, int n_in,
                              void* d_out, int out_size) {
    const float* x  = (const float*)d_in[0];
    const float* Wb = (const float*)d_in[1];
    const float* Wc = (const float*)d_in[2];
    const float* gb = (const float*)d_in[3];
    const float* bb = (const float*)d_in[4];
    const float* gc = (const float*)d_in[5];
    const float* bc = (const float*)d_in[6];
    float* out = (float*)d_out;

    k_down<<<NB * NC, 256>>>(x);
    k_mma<<<dim3(NCH, NB, 2), 256>>>(Wb, Wc);
    k_finish<<<dim3(NC, NB), 160>>>(gb, bb, gc, bc);
    k_final<<<dim3(NB * NC, 4), 256>>>(out);
}